// round 13
// baseline (speedup 1.0000x reference)
#include <cuda_runtime.h>

// LELoss: loss = S1/B + 1.1*S2/B + 0.1*S3/400
//   S1 = sum (x - decoded)^2              over [8192,1024]
//   S2 = sum (encoded - latent@rsrA^T)^2  over [8192,128], I=20
//   S3 = sum (rsrA^T rsrA - I)^2          over [20,20], E=128
// kNN/top_k in the reference is dead code (result unused).
//
// R10: same single-launch structure as R6 (18.9us best), but Part A unroll
// reduced 4x -> 2x: 16 live float4 (64 regs) was pushing the kernel to
// 116 regs = 2 CTAs/SM (occ 24.8%, DRAM 37%, latency-bound). 8 live float4
// should land ~72-84 regs -> 3+ CTAs/SM -> more warps -> more loads in
// flight -> higher DRAM%.

#define B_DIM   8192
#define D_DIM   1024
#define E_DIM   128
#define I_DIM   20
#define THREADS 256
#define NBLK    592

#define N4_A    ((B_DIM * D_DIM) / 4)   // 2,097,152 float4 pairs
#define N4_B    ((B_DIM * E_DIM) / 4)   // 262,144 float4 of encoded

// 0.1 * B / (I*I): pre-scales S3 so epilogue only divides by B once
#define S3_SCALE (0.1f * (float)B_DIM / (float)(I_DIM * I_DIM))

__device__ float         g_partials[NBLK];
__device__ unsigned int  g_count = 0;   // atomicInc wraps to 0 -> replay-safe

__global__ __launch_bounds__(THREADS) void loss_fused_kernel(
    const float* __restrict__ x,
    const float* __restrict__ encoded,
    const float* __restrict__ latent,
    const float* __restrict__ decoded,
    const float* __restrict__ rsrA,
    float* __restrict__ out)
{
    __shared__ float rs[I_DIM * E_DIM];   // rsrA transposed: rs[i*128 + e]

    const int tid    = threadIdx.x;
    const int g      = blockIdx.x * THREADS + tid;
    const int stride = NBLK * THREADS;

    // Stage rsrA transposed into shared (10 KB)
    for (int j = tid; j < I_DIM * E_DIM; j += THREADS) {
        int i = j >> 7;          // j / 128
        int e = j & (E_DIM - 1); // j % 128
        rs[j] = rsrA[e * I_DIM + i];
    }

    // ---- Part A: S1 = sum (x - decoded)^2, float4, 2-way unrolled ----
    const float4* __restrict__ x4 = (const float4*)x;
    const float4* __restrict__ d4 = (const float4*)decoded;

    float s1 = 0.0f;
    int i = g;
    for (; i + stride < N4_A; i += 2 * stride) {
        float4 a0 = x4[i];
        float4 a1 = x4[i + stride];
        float4 b0 = d4[i];
        float4 b1 = d4[i + stride];
        float t;
        t = a0.x - b0.x; s1 += t * t;  t = a0.y - b0.y; s1 += t * t;
        t = a0.z - b0.z; s1 += t * t;  t = a0.w - b0.w; s1 += t * t;
        t = a1.x - b1.x; s1 += t * t;  t = a1.y - b1.y; s1 += t * t;
        t = a1.z - b1.z; s1 += t * t;  t = a1.w - b1.w; s1 += t * t;
    }
    for (; i < N4_A; i += stride) {
        float4 a = x4[i];
        float4 b = d4[i];
        float t;
        t = a.x - b.x; s1 += t * t;  t = a.y - b.y; s1 += t * t;
        t = a.z - b.z; s1 += t * t;  t = a.w - b.w; s1 += t * t;
    }

    __syncthreads();   // rs ready

    // ---- Part B: S2 = sum (encoded - latent @ rsrA^T)^2 ----
    const float4* __restrict__ enc4 = (const float4*)encoded;
    float s2 = 0.0f;
    for (int idx = g; idx < N4_B; idx += stride) {
        int b  = idx >> 5;           // 32 float4 per row
        int e  = (idx & 31) << 2;    // base e column
        const float* __restrict__ lrow = latent + b * I_DIM;
        float4 enc = enc4[idx];
        float a0 = -enc.x, a1 = -enc.y, a2 = -enc.z, a3 = -enc.w;
        #pragma unroll
        for (int k = 0; k < I_DIM; k++) {
            float l = lrow[k];                 // warp-broadcast, L1 hit
            const float* r = &rs[k * E_DIM + e];
            a0 += l * r[0];
            a1 += l * r[1];
            a2 += l * r[2];
            a3 += l * r[3];
        }
        s2 += a0 * a0 + a1 * a1 + a2 * a2 + a3 * a3;
    }

    float partial = s1 + 1.1f * s2;

    // ---- Block 0 only: S3 Gram residual, scaled, folded into partial ----
    if (blockIdx.x == 0) {
        float s3 = 0.0f;
        for (int pq = tid; pq < I_DIM * I_DIM; pq += THREADS) {
            int p = pq / I_DIM;
            int q = pq - p * I_DIM;
            float gacc = 0.0f;
            #pragma unroll 4
            for (int e = 0; e < E_DIM; e++)
                gacc += rsrA[e * I_DIM + p] * rsrA[e * I_DIM + q];
            if (p == q) gacc -= 1.0f;
            s3 += gacc * gacc;
        }
        partial += S3_SCALE * s3;
    }

    // ---- Block reduction (deterministic tree) ----
    __shared__ float red[THREADS];
    red[tid] = partial;
    __syncthreads();
    #pragma unroll
    for (int off = THREADS / 2; off > 0; off >>= 1) {
        if (tid < off) red[tid] += red[tid + off];
        __syncthreads();
    }

    // ---- Last-block epilogue: sum 592 floats, divide, store ----
    __shared__ bool is_last;
    if (tid == 0) {
        g_partials[blockIdx.x] = red[0];
        __threadfence();
        unsigned int prev = atomicInc(&g_count, NBLK - 1);  // wraps -> replay-safe
        is_last = (prev == NBLK - 1);
    }
    __syncthreads();

    if (is_last) {
        float sum = 0.0f;
        for (int j = tid; j < NBLK; j += THREADS)  // fixed order -> deterministic
            sum += g_partials[j];
        red[tid] = sum;
        __syncthreads();
        #pragma unroll
        for (int off = THREADS / 2; off > 0; off >>= 1) {
            if (tid < off) red[tid] += red[tid + off];
            __syncthreads();
        }
        if (tid == 0)
            out[0] = red[0] / (float)B_DIM;
    }
}

extern "C" void kernel_launch(void* const* d_in, const int* in_sizes, int n_in,
                              void* d_out, int out_size) {
    const float* x       = (const float*)d_in[0];
    const float* encoded = (const float*)d_in[1];
    const float* latent  = (const float*)d_in[2];
    const float* decoded = (const float*)d_in[3];
    const float* rsrA    = (const float*)d_in[4];
    float* out = (float*)d_out;

    loss_fused_kernel<<<NBLK, THREADS>>>(x, encoded, latent, decoded, rsrA, out);
}